// round 15
// baseline (speedup 1.0000x reference)
#include <cuda_runtime.h>
#include <math.h>

#define EPSF 1.1920929e-07f
typedef unsigned long long ull;

// ---------------- f32x2 packed-FMA helpers (sm_103a) ----------------
__device__ __forceinline__ ull f2pk(float a, float b) {
    ull r; asm("mov.b64 %0, {%1,%2};" : "=l"(r) : "f"(a), "f"(b)); return r;
}
__device__ __forceinline__ ull ffma2(ull a, ull b, ull c) {
    ull d; asm("fma.rn.f32x2 %0, %1, %2, %3;" : "=l"(d) : "l"(a), "l"(b), "l"(c)); return d;
}
__device__ __forceinline__ float2 f2up(ull v) {
    float2 f; asm("mov.b64 {%0,%1}, %2;" : "=f"(f.x), "=f"(f.y) : "l"(v)); return f;
}

// ---------------- scratch (__device__ globals; no allocations) ----------------
__device__ float d_logits[4096];                 // (8,512)
__device__ int   d_topk[32];                     // (8,4) sorted ascending
__device__ float d_Qb[8 * 8 * 65 * 128];         // (bh, s, c) rope+rms+tao q
__device__ float d_Kb[8 * 8 * 65 * 128];         // (bh, s, c)
__device__ float d_Vb[8 * 8 * 65 * 128];         // (bh, s, c)
__device__ float d_g[8 * 64 * 1024];             // gate logits (b, r, h, c)
__device__ float d_yg[8 * 64 * 1024];            // gated attention output

// ---------------- K1: per-patch score logit; one warp per patch ----------------
__global__ __launch_bounds__(256) void k_score(const float* __restrict__ x,
                                               const float* __restrict__ pw) {
    int wid = threadIdx.x >> 5, lane = threadIdx.x & 31;
    int pid = blockIdx.x * 8 + wid;              // 512 blocks * 8 warps = 4096 patches
    const float4* xv = (const float4*)(x + (size_t)pid * 2048);
    const float4* pv = (const float4*)pw;
    float ss = 0.f, dp = 0.f;
#pragma unroll
    for (int i = 0; i < 16; i++) {
        float4 v = xv[i * 32 + lane];
        float4 w = pv[i * 32 + lane];
        ss += v.x * v.x + v.y * v.y + v.z * v.z + v.w * v.w;
        dp += v.x * w.x + v.y * w.y + v.z * w.z + v.w * w.w;
    }
#pragma unroll
    for (int o = 16; o; o >>= 1) {
        ss += __shfl_xor_sync(0xffffffffu, ss, o);
        dp += __shfl_xor_sync(0xffffffffu, dp, o);
    }
    if (lane == 0) d_logits[pid] = dp * rsqrtf(ss * (1.0f / 2048.0f) + EPSF);
}

// ---------------- K2: block0 = top-4 per batch; block1 = sink rows ----------------
__global__ __launch_bounds__(256) void k_topk_sink(const float* __restrict__ sink,
                                                   const float* __restrict__ tao) {
    int wid = threadIdx.x >> 5, lane = threadIdx.x & 31;
    if (blockIdx.x == 0) {
        int b = wid;
        float v[16];
#pragma unroll
        for (int i = 0; i < 16; i++) v[i] = d_logits[b * 512 + i * 32 + lane];
        int got[4];
#pragma unroll
        for (int r = 0; r < 4; r++) {
            float bv = -1e30f; int bi = 1 << 30;
#pragma unroll
            for (int i = 0; i < 16; i++) {
                int idx = i * 32 + lane;
                if (v[i] > bv || (v[i] == bv && idx < bi)) { bv = v[i]; bi = idx; }
            }
#pragma unroll
            for (int o = 16; o; o >>= 1) {
                float ov = __shfl_xor_sync(0xffffffffu, bv, o);
                int   oi = __shfl_xor_sync(0xffffffffu, bi, o);
                if (ov > bv || (ov == bv && oi < bi)) { bv = ov; bi = oi; }
            }
            got[r] = bi;
            if ((bi & 31) == lane) v[bi >> 5] = -1e30f;
        }
        if (lane == 0) {
#pragma unroll
            for (int i = 0; i < 4; i++)
#pragma unroll
                for (int j = 0; j < 3; j++)
                    if (got[j + 1] < got[j]) { int t = got[j]; got[j] = got[j + 1]; got[j + 1] = t; }
#pragma unroll
            for (int i = 0; i < 4; i++) d_topk[b * 4 + i] = got[i];
        }
    } else {
        // sink row s=0 per head (rope at s=0 is identity): Q/K = rmsnorm(sink)*tao, V = sink
        int h = wid;
        int c0 = lane * 4;
        float4 v = *(const float4*)(sink + h * 128 + c0);
        float ss = v.x * v.x + v.y * v.y + v.z * v.z + v.w * v.w;
#pragma unroll
        for (int o = 16; o; o >>= 1) ss += __shfl_xor_sync(0xffffffffu, ss, o);
        float n = rsqrtf(ss * (1.f / 128.f) + EPSF);
        float nq = n * tao[0], nk = n * tao[1];
        float4 q = make_float4(v.x * nq, v.y * nq, v.z * nq, v.w * nq);
        float4 k = make_float4(v.x * nk, v.y * nk, v.z * nk, v.w * nk);
#pragma unroll
        for (int b = 0; b < 8; b++) {
            size_t off = ((size_t)((b * 8 + h) * 65)) * 128 + c0;
            *(float4*)(d_Qb + off) = q;
            *(float4*)(d_Kb + off) = k;
            *(float4*)(d_Vb + off) = v;
        }
    }
}

// ---------------- K3: qkvg GEMM fused with rope+rmsnorm+tao epilogue ----------------
// grid (32 n-tiles, 8 batches), 256 threads; tile M=64 x N=128, K chunks of 32.
// Double-buffered: prefetch next kc chunk into registers during compute.
__global__ __launch_bounds__(256) void k_qkvg(const float* __restrict__ x,
                                              const float* __restrict__ W,
                                              const float* __restrict__ cosb,
                                              const float* __restrict__ sinb,
                                              const float* __restrict__ tao) {
    int nt = blockIdx.x, b = blockIdx.y;
    int tid = threadIdx.x;
    __shared__ __align__(16) float Xs[32][68];    // [k][m]
    __shared__ __align__(16) float Ws[32][132];   // [k][n]
    __shared__ int toks[64];
    if (tid < 64) toks[tid] = d_topk[b * 4 + (tid >> 4)] * 16 + (tid & 15);
    __syncthreads();
    int tx = tid & 15, ty = tid >> 4;
    int m0 = ty * 4, n0 = tx * 8;

    int mA = tid >> 3,            kqA = tid & 7;
    int mB = (tid + 256) >> 3,    kqB = (tid + 256) & 7;
    const float* xA = x + ((size_t)(b * 8192 + toks[mA])) * 128 + kqA * 4;
    const float* xB = x + ((size_t)(b * 8192 + toks[mB])) * 128 + kqB * 4;
    const float* wP[4];
    int cW[4], kqW[4];
#pragma unroll
    for (int jj = 0; jj < 4; jj++) {
        int idx = tid + jj * 256;
        cW[jj] = idx >> 3; kqW[jj] = idx & 7;
        wP[jj] = W + ((size_t)(nt * 128 + cW[jj])) * 128 + kqW[jj] * 4;
    }

    float4 xr0, xr1, wr[4];
    xr0 = *(const float4*)(xA);
    xr1 = *(const float4*)(xB);
#pragma unroll
    for (int jj = 0; jj < 4; jj++) wr[jj] = *(const float4*)(wP[jj]);

    ull acc[4][4];
#pragma unroll
    for (int i = 0; i < 4; i++)
#pragma unroll
        for (int j = 0; j < 4; j++) acc[i][j] = 0ull;

#pragma unroll 1
    for (int kc = 0; kc < 4; kc++) {
        Xs[kqA * 4 + 0][mA] = xr0.x; Xs[kqA * 4 + 1][mA] = xr0.y;
        Xs[kqA * 4 + 2][mA] = xr0.z; Xs[kqA * 4 + 3][mA] = xr0.w;
        Xs[kqB * 4 + 0][mB] = xr1.x; Xs[kqB * 4 + 1][mB] = xr1.y;
        Xs[kqB * 4 + 2][mB] = xr1.z; Xs[kqB * 4 + 3][mB] = xr1.w;
#pragma unroll
        for (int jj = 0; jj < 4; jj++) {
            Ws[kqW[jj] * 4 + 0][cW[jj]] = wr[jj].x; Ws[kqW[jj] * 4 + 1][cW[jj]] = wr[jj].y;
            Ws[kqW[jj] * 4 + 2][cW[jj]] = wr[jj].z; Ws[kqW[jj] * 4 + 3][cW[jj]] = wr[jj].w;
        }
        __syncthreads();
        if (kc < 3) {
            int off = (kc + 1) * 32;
            xr0 = *(const float4*)(xA + off);
            xr1 = *(const float4*)(xB + off);
#pragma unroll
            for (int jj = 0; jj < 4; jj++) wr[jj] = *(const float4*)(wP[jj] + off);
        }
#pragma unroll
        for (int k = 0; k < 32; k++) {
            float4 xv = *(const float4*)&Xs[k][m0];
            ull xb0 = f2pk(xv.x, xv.x), xb1 = f2pk(xv.y, xv.y);
            ull xb2 = f2pk(xv.z, xv.z), xb3 = f2pk(xv.w, xv.w);
            const ull* wp = (const ull*)&Ws[k][n0];
            ull w0 = wp[0], w1 = wp[1], w2 = wp[2], w3 = wp[3];
            acc[0][0] = ffma2(xb0, w0, acc[0][0]); acc[0][1] = ffma2(xb0, w1, acc[0][1]);
            acc[0][2] = ffma2(xb0, w2, acc[0][2]); acc[0][3] = ffma2(xb0, w3, acc[0][3]);
            acc[1][0] = ffma2(xb1, w0, acc[1][0]); acc[1][1] = ffma2(xb1, w1, acc[1][1]);
            acc[1][2] = ffma2(xb1, w2, acc[1][2]); acc[1][3] = ffma2(xb1, w3, acc[1][3]);
            acc[2][0] = ffma2(xb2, w0, acc[2][0]); acc[2][1] = ffma2(xb2, w1, acc[2][1]);
            acc[2][2] = ffma2(xb2, w2, acc[2][2]); acc[2][3] = ffma2(xb2, w3, acc[2][3]);
            acc[3][0] = ffma2(xb3, w0, acc[3][0]); acc[3][1] = ffma2(xb3, w1, acc[3][1]);
            acc[3][2] = ffma2(xb3, w2, acc[3][2]); acc[3][3] = ffma2(xb3, w3, acc[3][3]);
        }
        __syncthreads();
    }

    // ---- fused epilogue ----
    int cb = nt >> 3, h = nt & 7;
    int cat = ty & 3;                             // 0=q 1=k 2=v 3=g (half-warp-uniform)
    int p = ty >> 2;
    int bh = b * 8 + h;
#pragma unroll
    for (int i = 0; i < 4; i++) {
        float r[8];
#pragma unroll
        for (int j = 0; j < 4; j++) {
            float2 f = f2up(acc[i][j]);
            r[2 * j] = f.x; r[2 * j + 1] = f.y;
        }
        int s0 = p * 16 + i * 4 + cb;             // row index within (b,h), 0..63
        int s = s0 + 1;
        if (cat < 2) {                            // q or k: rope + rmsnorm + tao
            float other[8];
#pragma unroll
            for (int c = 0; c < 8; c++) other[c] = __shfl_xor_sync(0xffffffffu, r[c], 8);
            int d0 = n0 & 63;
            float4 ca = *(const float4*)(cosb + s * 64 + d0);
            float4 cbv = *(const float4*)(cosb + s * 64 + d0 + 4);
            float4 sa = *(const float4*)(sinb + s * 64 + d0);
            float4 sb = *(const float4*)(sinb + s * 64 + d0 + 4);
            float cs[8] = {ca.x, ca.y, ca.z, ca.w, cbv.x, cbv.y, cbv.z, cbv.w};
            float sn[8] = {sa.x, sa.y, sa.z, sa.w, sb.x, sb.y, sb.z, sb.w};
            float sgn = (tx < 8) ? 1.f : -1.f;
            float rv[8], ssq = 0.f;
#pragma unroll
            for (int c = 0; c < 8; c++) {
                rv[c] = fmaf(r[c], cs[c], sgn * other[c] * sn[c]);
                ssq += rv[c] * rv[c];
            }
#pragma unroll
            for (int o = 8; o; o >>= 1) ssq += __shfl_xor_sync(0xffffffffu, ssq, o);
            float nrm = rsqrtf(ssq * (1.f / 128.f) + EPSF) * tao[cat];
            float* dst = (cat == 0 ? d_Qb : d_Kb) + ((size_t)bh * 65 + s) * 128 + n0;
            *(float4*)dst = make_float4(rv[0] * nrm, rv[1] * nrm, rv[2] * nrm, rv[3] * nrm);
            *(float4*)(dst + 4) = make_float4(rv[4] * nrm, rv[5] * nrm, rv[6] * nrm, rv[7] * nrm);
        } else if (cat == 2) {                    // v: raw
            float* dst = d_Vb + ((size_t)bh * 65 + s) * 128 + n0;
            *(float4*)dst = make_float4(r[0], r[1], r[2], r[3]);
            *(float4*)(dst + 4) = make_float4(r[4], r[5], r[6], r[7]);
        } else {                                  // g: raw gate logits
            float* dst = d_g + ((size_t)(b * 64 + s0)) * 1024 + h * 128 + n0;
            *(float4*)dst = make_float4(r[0], r[1], r[2], r[3]);
            *(float4*)(dst + 4) = make_float4(r[4], r[5], r[6], r[7]);
        }
    }
}

// ---------------- K5: causal attention, single-load-phase design ----------------
// grid (8 chunks of 8 rows, 64 bh), 256 threads (8 warps). Whole K tile + Q rows
// staged in one bulk load -> ONE __syncthreads -> register QK (warp=row,
// lane=2 t-slots) -> register softmax -> PV from global. 2 phases total.
__global__ __launch_bounds__(256) void k_attn() {
    __shared__ __align__(16) float Qc[128][12];   // [k][row]  (8 rows used)
    __shared__ __align__(16) float Kc[128 * 68];  // [k][t]
    __shared__ float Ps[8 * 68];                  // probs per row
    int chunk = blockIdx.x, bh = blockIdx.y;
    int b = bh >> 3, h = bh & 7;
    int tid = threadIdx.x;
    int wid = tid >> 5, lane = tid & 31;
    int rbase = chunk * 8;
    int text = rbase + 9;                         // 9,17,...,65
    const float* Qg = d_Qb + (size_t)bh * 65 * 128;
    const float* Kg = d_Kb + (size_t)bh * 65 * 128;
    const float* Vg = d_Vb + (size_t)bh * 65 * 128;

    // ---- bulk load: Q (8 rows) + K (text rows), all LDGs in flight ----
    {   // Q: warp wid loads row wid
        int cq = lane;
        float4 qv = *(const float4*)(Qg + (size_t)(rbase + wid + 1) * 128 + cq * 4);
        Qc[cq * 4 + 0][wid] = qv.x; Qc[cq * 4 + 1][wid] = qv.y;
        Qc[cq * 4 + 2][wid] = qv.z; Qc[cq * 4 + 3][wid] = qv.w;
    }
    for (int idx = tid; idx < text * 32; idx += 256) {
        int t = idx >> 5, cq = idx & 31;
        float4 kv = *(const float4*)(Kg + (size_t)t * 128 + cq * 4);
        Kc[(cq * 4 + 0) * 68 + t] = kv.x; Kc[(cq * 4 + 1) * 68 + t] = kv.y;
        Kc[(cq * 4 + 2) * 68 + t] = kv.z; Kc[(cq * 4 + 3) * 68 + t] = kv.w;
    }
    __syncthreads();

    // ---- QK: warp owns row wid; lane owns t = 2*lane, 2*lane+1 ----
    int r = wid;
    int t0 = lane * 2;
    ull accA = 0ull, accB = 0ull;                 // even/odd k chains
#pragma unroll 8
    for (int k = 0; k < 128; k += 2) {
        float q0 = Qc[k][r];                      // broadcast
        float q1 = Qc[k + 1][r];
        ull kv0 = *(const ull*)&Kc[k * 68 + t0];
        ull kv1 = *(const ull*)&Kc[(k + 1) * 68 + t0];
        accA = ffma2(kv0, f2pk(q0, q0), accA);
        accB = ffma2(kv1, f2pk(q1, q1), accB);
    }
    float2 fa = f2up(accA), fb = f2up(accB);
    float sx = fa.x + fb.x, sy = fa.y + fb.y;

    // extra t=64 score (only chunk 7, row 7 has s=64)
    int s = rbase + r + 1;
    float sc64 = 0.f;
    if (chunk == 7 && r == 7) {
        float part = 0.f;
#pragma unroll
        for (int j = 0; j < 4; j++)
            part += Qc[lane * 4 + j][7] * Kc[(lane * 4 + j) * 68 + 64];
#pragma unroll
        for (int o = 16; o; o >>= 1) part += __shfl_xor_sync(0xffffffffu, part, o);
        sc64 = part;
    }

    // ---- register softmax (per warp) ----
    const float scl = 0.08838834764831845f;       // 1/sqrt(128)
    bool okx = (t0 <= s), oky = (t0 + 1 <= s);
    bool ok64 = (s == 64);
    float vx = okx ? sx * scl : -1e30f;
    float vy = oky ? sy * scl : -1e30f;
    float ve = ok64 ? sc64 * scl : -1e30f;        // warp-uniform
    float m = fmaxf(vx, vy);
#pragma unroll
    for (int o = 16; o; o >>= 1) m = fmaxf(m, __shfl_xor_sync(0xffffffffu, m, o));
    m = fmaxf(m, ve);
    float ex = okx ? __expf(vx - m) : 0.f;
    float ey = oky ? __expf(vy - m) : 0.f;
    float ee = ok64 ? __expf(ve - m) : 0.f;
    float sum = ex + ey;
#pragma unroll
    for (int o = 16; o; o >>= 1) sum += __shfl_xor_sync(0xffffffffu, sum, o);
    sum += ee;
    float inv = 1.f / sum;
    Ps[r * 68 + t0]     = ex * inv;
    Ps[r * 68 + t0 + 1] = ey * inv;
    if (lane == 0) Ps[r * 68 + 64] = ee * inv;
    __syncwarp();                                  // Ps row private to this warp

    // ---- PV: lane owns channels c0..c0+3; V rows from global (L1-shared) ----
    int c0 = lane * 4;
    ull y0 = 0ull, y1 = 0ull;
    const float* P = &Ps[r * 68];
#pragma unroll 4
    for (int t = 0; t < text; t++) {
        const ull* vp = (const ull*)(Vg + (size_t)t * 128 + c0);
        ull v0 = vp[0], v1 = vp[1];
        float p = P[t];
        ull pb = f2pk(p, p);
        y0 = ffma2(pb, v0, y0);
        y1 = ffma2(pb, v1, y1);
    }

    // ---- gate with sigmoid(g) and store ----
    int rg = rbase + r;                            // global row 0..63 (= s-1)
    float4 g4 = *(const float4*)(d_g + ((size_t)(b * 64 + rg)) * 1024 + h * 128 + c0);
    float2 ya = f2up(y0), yb = f2up(y1);
    float4 o;
    o.x = ya.x / (1.f + __expf(-g4.x));
    o.y = ya.y / (1.f + __expf(-g4.y));
    o.z = yb.x / (1.f + __expf(-g4.z));
    o.w = yb.y / (1.f + __expf(-g4.w));
    *(float4*)(d_yg + ((size_t)(b * 64 + rg)) * 1024 + h * 128 + c0) = o;
}

// ---------------- K6: output GEMM, split-K=8, atomicAdd into out (f32x2) ----------------
__global__ __launch_bounds__(128) void k_out(const float* __restrict__ Wout,
                                             float* __restrict__ out) {
    int mt = blockIdx.x, nt = blockIdx.y, kc = blockIdx.z;
    __shared__ __align__(16) float Ys[32][68];
    __shared__ __align__(16) float Ws[32][68];
    int tid = threadIdx.x;
    int tx = tid & 7, ty = tid >> 3;
    int m0 = ty * 4, n0 = tx * 8;
    ull acc[4][4];
#pragma unroll
    for (int i = 0; i < 4; i++)
#pragma unroll
        for (int j = 0; j < 4; j++) acc[i][j] = 0ull;

#pragma unroll 1
    for (int ck = 0; ck < 4; ck++) {
        int kbase = kc * 128 + ck * 32;
#pragma unroll
        for (int jj = 0; jj < 4; jj++) {
            int idx = tid + jj * 128;
            int m = idx >> 3, kq = idx & 7;
            float4 v = *(const float4*)(d_yg + (size_t)(mt * 64 + m) * 1024 + kbase + kq * 4);
            Ys[kq * 4 + 0][m] = v.x; Ys[kq * 4 + 1][m] = v.y;
            Ys[kq * 4 + 2][m] = v.z; Ys[kq * 4 + 3][m] = v.w;
            float4 w = *(const float4*)(Wout + (size_t)(nt * 64 + m) * 1024 + kbase + kq * 4);
            Ws[kq * 4 + 0][m] = w.x; Ws[kq * 4 + 1][m] = w.y;
            Ws[kq * 4 + 2][m] = w.z; Ws[kq * 4 + 3][m] = w.w;
        }
        __syncthreads();
#pragma unroll
        for (int k = 0; k < 32; k++) {
            float4 yv = *(const float4*)&Ys[k][m0];
            ull yb0 = f2pk(yv.x, yv.x), yb1 = f2pk(yv.y, yv.y);
            ull yb2 = f2pk(yv.z, yv.z), yb3 = f2pk(yv.w, yv.w);
            const ull* wp = (const ull*)&Ws[k][n0];
            ull w0 = wp[0], w1 = wp[1], w2 = wp[2], w3 = wp[3];
            acc[0][0] = ffma2(yb0, w0, acc[0][0]); acc[0][1] = ffma2(yb0, w1, acc[0][1]);
            acc[0][2] = ffma2(yb0, w2, acc[0][2]); acc[0][3] = ffma2(yb0, w3, acc[0][3]);
            acc[1][0] = ffma2(yb1, w0, acc[1][0]); acc[1][1] = ffma2(yb1, w1, acc[1][1]);
            acc[1][2] = ffma2(yb1, w2, acc[1][2]); acc[1][3] = ffma2(yb1, w3, acc[1][3]);
            acc[2][0] = ffma2(yb2, w0, acc[2][0]); acc[2][1] = ffma2(yb2, w1, acc[2][1]);
            acc[2][2] = ffma2(yb2, w2, acc[2][2]); acc[2][3] = ffma2(yb2, w3, acc[2][3]);
            acc[3][0] = ffma2(yb3, w0, acc[3][0]); acc[3][1] = ffma2(yb3, w1, acc[3][1]);
            acc[3][2] = ffma2(yb3, w2, acc[3][2]); acc[3][3] = ffma2(yb3, w3, acc[3][3]);
        }
        __syncthreads();
    }
#pragma unroll
    for (int i = 0; i < 4; i++) {
        float* dst = out + (size_t)(mt * 64 + m0 + i) * 128 + nt * 64 + n0;
#pragma unroll
        for (int j = 0; j < 4; j++) {
            float2 f = f2up(acc[i][j]);
            atomicAdd(dst + 2 * j,     f.x);
            atomicAdd(dst + 2 * j + 1, f.y);
        }
    }
}

// ---------------- launch ----------------
extern "C" void kernel_launch(void* const* d_in, const int* in_sizes, int n_in,
                              void* d_out, int out_size) {
    const float* x     = (const float*)d_in[0];
    const float* cosb  = (const float*)d_in[1];
    const float* sinb  = (const float*)d_in[2];
    const float* sink  = (const float*)d_in[3];
    const float* Wqkvg = (const float*)d_in[4];
    const float* pw    = (const float*)d_in[5];
    const float* Wout  = (const float*)d_in[6];
    const float* tao   = (const float*)d_in[7];
    float* out = (float*)d_out;

    cudaMemsetAsync(out, 0, (size_t)out_size * sizeof(float));
    k_score<<<512, 256>>>(x, pw);
    k_topk_sink<<<2, 256>>>(sink, tao);
    k_qkvg<<<dim3(32, 8), 256>>>(x, Wqkvg, cosb, sinb, tao);
    k_attn<<<dim3(8, 64), 256>>>();
    k_out<<<dim3(8, 2, 8), 128>>>(Wout, out);
}

// round 17
// speedup vs baseline: 1.2829x; 1.2829x over previous
#include <cuda_runtime.h>
#include <math.h>

#define EPSF 1.1920929e-07f
typedef unsigned long long ull;

// ---------------- f32x2 packed-FMA helpers (sm_103a) ----------------
__device__ __forceinline__ ull f2pk(float a, float b) {
    ull r; asm("mov.b64 %0, {%1,%2};" : "=l"(r) : "f"(a), "f"(b)); return r;
}
__device__ __forceinline__ ull ffma2(ull a, ull b, ull c) {
    ull d; asm("fma.rn.f32x2 %0, %1, %2, %3;" : "=l"(d) : "l"(a), "l"(b), "l"(c)); return d;
}
__device__ __forceinline__ float2 f2up(ull v) {
    float2 f; asm("mov.b64 {%0,%1}, %2;" : "=f"(f.x), "=f"(f.y) : "l"(v)); return f;
}

// ---------------- scratch (__device__ globals; no allocations) ----------------
__device__ float d_logits[4096];                 // (8,512)
__device__ float d_Qb[8 * 8 * 65 * 128];         // (bh, s, c) rope+rms+tao q
__device__ float d_Kb[8 * 8 * 65 * 128];         // (bh, s, c)
__device__ float d_Vb[8 * 8 * 65 * 128];         // (bh, s, c)
__device__ float d_g[8 * 64 * 1024];             // gate logits (b, r, h, c)
__device__ float d_yg[8 * 64 * 1024];            // gated attention output

// ---------------- K1: per-patch score logit; one warp per patch; zeroes out ----------------
__global__ __launch_bounds__(256) void k_score(const float* __restrict__ x,
                                               const float* __restrict__ pw,
                                               float* __restrict__ out) {
    // zero this block's slice of out (65536 floats / 512 blocks = 128 floats)
    if (threadIdx.x < 32)
        *(float4*)(out + blockIdx.x * 128 + threadIdx.x * 4) = make_float4(0.f, 0.f, 0.f, 0.f);

    int wid = threadIdx.x >> 5, lane = threadIdx.x & 31;
    int pid = blockIdx.x * 8 + wid;              // 512 blocks * 8 warps = 4096 patches
    const float4* xv = (const float4*)(x + (size_t)pid * 2048);
    const float4* pv = (const float4*)pw;
    float ss = 0.f, dp = 0.f;
#pragma unroll
    for (int i = 0; i < 16; i++) {
        float4 v = xv[i * 32 + lane];
        float4 w = pv[i * 32 + lane];
        ss += v.x * v.x + v.y * v.y + v.z * v.z + v.w * v.w;
        dp += v.x * w.x + v.y * w.y + v.z * w.z + v.w * w.w;
    }
#pragma unroll
    for (int o = 16; o; o >>= 1) {
        ss += __shfl_xor_sync(0xffffffffu, ss, o);
        dp += __shfl_xor_sync(0xffffffffu, dp, o);
    }
    if (lane == 0) d_logits[pid] = dp * rsqrtf(ss * (1.0f / 2048.0f) + EPSF);
}

// ---------------- K3: qkvg GEMM + inline top-k + rope/rms/tao epilogue + sink rows ----------------
// grid (32 n-tiles, 8 batches), 256 threads; tile M=64 x N=128, K chunks of 32.
__global__ __launch_bounds__(256) void k_qkvg(const float* __restrict__ x,
                                              const float* __restrict__ W,
                                              const float* __restrict__ cosb,
                                              const float* __restrict__ sinb,
                                              const float* __restrict__ tao,
                                              const float* __restrict__ sink) {
    int nt = blockIdx.x, b = blockIdx.y;
    int tid = threadIdx.x;
    __shared__ __align__(16) float Xs[32][68];    // [k][m]
    __shared__ __align__(16) float Ws[32][132];   // [k][n]
    __shared__ int toks[64];
    int wid = tid >> 5, lane = tid & 31;

    // ---- inline top-4 of this batch's 512 logits (warp 0; same algo as before) ----
    if (wid == 0) {
        float v[16];
#pragma unroll
        for (int i = 0; i < 16; i++) v[i] = d_logits[b * 512 + i * 32 + lane];
        int got[4];
#pragma unroll
        for (int r = 0; r < 4; r++) {
            float bv = -1e30f; int bi = 1 << 30;
#pragma unroll
            for (int i = 0; i < 16; i++) {
                int idx = i * 32 + lane;
                if (v[i] > bv || (v[i] == bv && idx < bi)) { bv = v[i]; bi = idx; }
            }
#pragma unroll
            for (int o = 16; o; o >>= 1) {
                float ov = __shfl_xor_sync(0xffffffffu, bv, o);
                int   oi = __shfl_xor_sync(0xffffffffu, bi, o);
                if (ov > bv || (ov == bv && oi < bi)) { bv = ov; bi = oi; }
            }
            got[r] = bi;
            if ((bi & 31) == lane) v[bi >> 5] = -1e30f;
        }
        // sort ascending (all lanes hold identical got[])
#pragma unroll
        for (int i = 0; i < 4; i++)
#pragma unroll
            for (int j = 0; j < 3; j++)
                if (got[j + 1] < got[j]) { int t = got[j]; got[j] = got[j + 1]; got[j + 1] = t; }
        toks[lane]      = got[lane >> 4] * 16 + (lane & 15);
        toks[lane + 32] = got[2 + (lane >> 4)] * 16 + (lane & 15);
    }
    __syncthreads();

    int tx = tid & 15, ty = tid >> 4;
    int m0 = ty * 4, n0 = tx * 8;
    ull acc[4][4];
#pragma unroll
    for (int i = 0; i < 4; i++)
#pragma unroll
        for (int j = 0; j < 4; j++) acc[i][j] = 0ull;

#pragma unroll 1
    for (int kc = 0; kc < 4; kc++) {
#pragma unroll
        for (int jj = 0; jj < 2; jj++) {
            int idx = tid + jj * 256;
            int m = idx >> 3, kq = idx & 7;
            float4 v = *(const float4*)(x + ((size_t)(b * 8192 + toks[m])) * 128 + kc * 32 + kq * 4);
            Xs[kq * 4 + 0][m] = v.x; Xs[kq * 4 + 1][m] = v.y;
            Xs[kq * 4 + 2][m] = v.z; Xs[kq * 4 + 3][m] = v.w;
        }
#pragma unroll
        for (int jj = 0; jj < 4; jj++) {
            int idx = tid + jj * 256;
            int c = idx >> 3, kq = idx & 7;
            float4 v = *(const float4*)(W + ((size_t)(nt * 128 + c)) * 128 + kc * 32 + kq * 4);
            Ws[kq * 4 + 0][c] = v.x; Ws[kq * 4 + 1][c] = v.y;
            Ws[kq * 4 + 2][c] = v.z; Ws[kq * 4 + 3][c] = v.w;
        }
        __syncthreads();
#pragma unroll
        for (int k = 0; k < 32; k++) {
            float4 xv = *(const float4*)&Xs[k][m0];
            ull xb0 = f2pk(xv.x, xv.x), xb1 = f2pk(xv.y, xv.y);
            ull xb2 = f2pk(xv.z, xv.z), xb3 = f2pk(xv.w, xv.w);
            const ull* wp = (const ull*)&Ws[k][n0];
            ull w0 = wp[0], w1 = wp[1], w2 = wp[2], w3 = wp[3];
            acc[0][0] = ffma2(xb0, w0, acc[0][0]); acc[0][1] = ffma2(xb0, w1, acc[0][1]);
            acc[0][2] = ffma2(xb0, w2, acc[0][2]); acc[0][3] = ffma2(xb0, w3, acc[0][3]);
            acc[1][0] = ffma2(xb1, w0, acc[1][0]); acc[1][1] = ffma2(xb1, w1, acc[1][1]);
            acc[1][2] = ffma2(xb1, w2, acc[1][2]); acc[1][3] = ffma2(xb1, w3, acc[1][3]);
            acc[2][0] = ffma2(xb2, w0, acc[2][0]); acc[2][1] = ffma2(xb2, w1, acc[2][1]);
            acc[2][2] = ffma2(xb2, w2, acc[2][2]); acc[2][3] = ffma2(xb2, w3, acc[2][3]);
            acc[3][0] = ffma2(xb3, w0, acc[3][0]); acc[3][1] = ffma2(xb3, w1, acc[3][1]);
            acc[3][2] = ffma2(xb3, w2, acc[3][2]); acc[3][3] = ffma2(xb3, w3, acc[3][3]);
        }
        __syncthreads();
    }

    // ---- fused epilogue ----
    int cb = nt >> 3, h = nt & 7;
    int cat = ty & 3;                             // 0=q 1=k 2=v 3=g (half-warp-uniform)
    int p = ty >> 2;
    int bh = b * 8 + h;
#pragma unroll
    for (int i = 0; i < 4; i++) {
        float r[8];
#pragma unroll
        for (int j = 0; j < 4; j++) {
            float2 f = f2up(acc[i][j]);
            r[2 * j] = f.x; r[2 * j + 1] = f.y;
        }
        int s0 = p * 16 + i * 4 + cb;             // row index within (b,h), 0..63
        int s = s0 + 1;
        if (cat < 2) {                            // q or k: rope + rmsnorm + tao
            float other[8];
#pragma unroll
            for (int c = 0; c < 8; c++) other[c] = __shfl_xor_sync(0xffffffffu, r[c], 8);
            int d0 = n0 & 63;
            float4 ca = *(const float4*)(cosb + s * 64 + d0);
            float4 cbv = *(const float4*)(cosb + s * 64 + d0 + 4);
            float4 sa = *(const float4*)(sinb + s * 64 + d0);
            float4 sb = *(const float4*)(sinb + s * 64 + d0 + 4);
            float cs[8] = {ca.x, ca.y, ca.z, ca.w, cbv.x, cbv.y, cbv.z, cbv.w};
            float sn[8] = {sa.x, sa.y, sa.z, sa.w, sb.x, sb.y, sb.z, sb.w};
            float sgn = (tx < 8) ? 1.f : -1.f;
            float rv[8], ssq = 0.f;
#pragma unroll
            for (int c = 0; c < 8; c++) {
                rv[c] = fmaf(r[c], cs[c], sgn * other[c] * sn[c]);
                ssq += rv[c] * rv[c];
            }
#pragma unroll
            for (int o = 8; o; o >>= 1) ssq += __shfl_xor_sync(0xffffffffu, ssq, o);
            float nrm = rsqrtf(ssq * (1.f / 128.f) + EPSF) * tao[cat];
            float* dst = (cat == 0 ? d_Qb : d_Kb) + ((size_t)bh * 65 + s) * 128 + n0;
            *(float4*)dst = make_float4(rv[0] * nrm, rv[1] * nrm, rv[2] * nrm, rv[3] * nrm);
            *(float4*)(dst + 4) = make_float4(rv[4] * nrm, rv[5] * nrm, rv[6] * nrm, rv[7] * nrm);
        } else if (cat == 2) {                    // v: raw
            float* dst = d_Vb + ((size_t)bh * 65 + s) * 128 + n0;
            *(float4*)dst = make_float4(r[0], r[1], r[2], r[3]);
            *(float4*)(dst + 4) = make_float4(r[4], r[5], r[6], r[7]);
        } else {                                  // g: raw gate logits
            float* dst = d_g + ((size_t)(b * 64 + s0)) * 1024 + h * 128 + n0;
            *(float4*)dst = make_float4(r[0], r[1], r[2], r[3]);
            *(float4*)(dst + 4) = make_float4(r[4], r[5], r[6], r[7]);
        }
    }

    // ---- sink row s=0 for this (b,h): only blocks with cb==0 (nt==h) ----
    if (nt < 8 && tid < 32) {
        int c0 = tid * 4;
        float4 v = *(const float4*)(sink + nt * 128 + c0);
        float ss = v.x * v.x + v.y * v.y + v.z * v.z + v.w * v.w;
#pragma unroll
        for (int o = 16; o; o >>= 1) ss += __shfl_xor_sync(0xffffffffu, ss, o);
        float n = rsqrtf(ss * (1.f / 128.f) + EPSF);
        float nq = n * tao[0], nk = n * tao[1];
        size_t off = ((size_t)((b * 8 + nt) * 65)) * 128 + c0;
        *(float4*)(d_Qb + off) = make_float4(v.x * nq, v.y * nq, v.z * nq, v.w * nq);
        *(float4*)(d_Kb + off) = make_float4(v.x * nk, v.y * nk, v.z * nk, v.w * nk);
        *(float4*)(d_Vb + off) = v;
    }
}

// ---------------- K5: causal attention, 2 row-chunks per (b,h), f32x2 (round-6 best) ----------------
__global__ __launch_bounds__(256) void k_attn() {
    __shared__ __align__(16) float Ps[32 * 68];
    __shared__ __align__(16) float Buf[4224];     // Qc(32x36) + Kc(32x68); reused as Vc(32x132)
    float* Qc = Buf;
    float* Kc = Buf + 1152;
    int chunk = blockIdx.x, bh = blockIdx.y;
    int b = bh >> 3, h = bh & 7;
    int tid = threadIdx.x;
    int wid = tid >> 5, lane = tid & 31;
    const float* Qg = d_Qb + (size_t)bh * 65 * 128;
    const float* Kg = d_Kb + (size_t)bh * 65 * 128;
    const float* Vg = d_Vb + (size_t)bh * 65 * 128;
    int text = chunk ? 65 : 33;                   // t extent needed
    int r0 = wid * 4;
    int t0 = lane * 2;
    ull acc[2][2] = {0ull, 0ull, 0ull, 0ull};
    float e64 = 0.f;

#pragma unroll 1
    for (int kc = 0; kc < 4; kc++) {
        {
            int r = tid >> 3, kq = tid & 7;
            float4 qv = *(const float4*)(Qg + (size_t)(chunk * 32 + r + 1) * 128 + kc * 32 + kq * 4);
            Qc[(kq * 4 + 0) * 36 + r] = qv.x; Qc[(kq * 4 + 1) * 36 + r] = qv.y;
            Qc[(kq * 4 + 2) * 36 + r] = qv.z; Qc[(kq * 4 + 3) * 36 + r] = qv.w;
        }
        for (int idx = tid; idx < text * 8; idx += 256) {
            int t = idx >> 3, kq = idx & 7;
            float4 kv = *(const float4*)(Kg + (size_t)t * 128 + kc * 32 + kq * 4);
            Kc[(kq * 4 + 0) * 68 + t] = kv.x; Kc[(kq * 4 + 1) * 68 + t] = kv.y;
            Kc[(kq * 4 + 2) * 68 + t] = kv.z; Kc[(kq * 4 + 3) * 68 + t] = kv.w;
        }
        __syncthreads();
#pragma unroll
        for (int k = 0; k < 32; k++) {
            const ull* qp = (const ull*)&Qc[k * 36 + r0];
            ull q0 = qp[0], q1 = qp[1];
            float2 kv = *(const float2*)&Kc[k * 68 + t0];
            ull kb0 = f2pk(kv.x, kv.x), kb1 = f2pk(kv.y, kv.y);
            acc[0][0] = ffma2(q0, kb0, acc[0][0]); acc[0][1] = ffma2(q0, kb1, acc[0][1]);
            acc[1][0] = ffma2(q1, kb0, acc[1][0]); acc[1][1] = ffma2(q1, kb1, acc[1][1]);
        }
        if (chunk == 1 && tid == 0) {
#pragma unroll
            for (int k = 0; k < 32; k++) e64 += Qc[k * 36 + 31] * Kc[k * 68 + 64];
        }
        __syncthreads();
    }
    const float scl = 0.08838834764831845f;       // 1/sqrt(128)
#pragma unroll
    for (int p = 0; p < 2; p++)
#pragma unroll
        for (int j = 0; j < 2; j++) {
            float2 f = f2up(acc[p][j]);
            Ps[(r0 + 2 * p)     * 68 + t0 + j] = f.x * scl;
            Ps[(r0 + 2 * p + 1) * 68 + t0 + j] = f.y * scl;
        }
    if (chunk == 1 && tid == 0) Ps[31 * 68 + 64] = e64 * scl;
    __syncthreads();
    if (tid < 32) {
        int r = tid, s = chunk * 32 + r + 1;
        float m = -1e30f;
        for (int t = 0; t <= s; t++) m = fmaxf(m, Ps[r * 68 + t]);
        float sum = 0.f;
        for (int t = 0; t <= s; t++) { float e = __expf(Ps[r * 68 + t] - m); Ps[r * 68 + t] = e; sum += e; }
        float inv = 1.f / sum;
        for (int t = 0; t <= s; t++) Ps[r * 68 + t] *= inv;
        for (int t = s + 1; t < 65; t++) Ps[r * 68 + t] = 0.f;
    }
    __syncthreads();
    float* Vc = Buf;                              // [t][c] stride 132
    int c0 = lane * 4;
    ull y[4][2];
#pragma unroll
    for (int i = 0; i < 4; i++) { y[i][0] = 0ull; y[i][1] = 0ull; }
#pragma unroll 1
    for (int tc = 0; tc * 32 < text; tc++) {
        int tb = tc * 32;
        int tcnt = min(32, text - tb);
        for (int idx = tid; idx < tcnt * 32; idx += 256) {
            int tt = idx >> 5, kq = idx & 31;
            *(float4*)&Vc[tt * 132 + kq * 4] = *(const float4*)(Vg + (size_t)(tb + tt) * 128 + kq * 4);
        }
        __syncthreads();
        for (int tt = 0; tt < tcnt; tt++) {
            int t = tb + tt;
            float p0 = Ps[(r0 + 0) * 68 + t], p1 = Ps[(r0 + 1) * 68 + t];
            float p2 = Ps[(r0 + 2) * 68 + t], p3 = Ps[(r0 + 3) * 68 + t];
            ull pb0 = f2pk(p0, p0), pb1 = f2pk(p1, p1);
            ull pb2 = f2pk(p2, p2), pb3 = f2pk(p3, p3);
            const ull* vp = (const ull*)&Vc[tt * 132 + c0];
            ull v0 = vp[0], v1 = vp[1];
            y[0][0] = ffma2(pb0, v0, y[0][0]); y[0][1] = ffma2(pb0, v1, y[0][1]);
            y[1][0] = ffma2(pb1, v0, y[1][0]); y[1][1] = ffma2(pb1, v1, y[1][1]);
            y[2][0] = ffma2(pb2, v0, y[2][0]); y[2][1] = ffma2(pb2, v1, y[2][1]);
            y[3][0] = ffma2(pb3, v0, y[3][0]); y[3][1] = ffma2(pb3, v1, y[3][1]);
        }
        __syncthreads();
    }
#pragma unroll
    for (int i = 0; i < 4; i++) {
        int rg = chunk * 32 + r0 + i;
        const float* gb = d_g + ((size_t)(b * 64 + rg)) * 1024 + h * 128 + c0;
        float4 g4 = *(const float4*)gb;
        float2 a = f2up(y[i][0]), cpr = f2up(y[i][1]);
        float4 o;
        o.x = a.x   / (1.f + __expf(-g4.x));
        o.y = a.y   / (1.f + __expf(-g4.y));
        o.z = cpr.x / (1.f + __expf(-g4.z));
        o.w = cpr.y / (1.f + __expf(-g4.w));
        *(float4*)(d_yg + ((size_t)(b * 64 + rg)) * 1024 + h * 128 + c0) = o;
    }
}

// ---------------- K6: output GEMM, split-K=8, atomicAdd into out (f32x2) ----------------
__global__ __launch_bounds__(128) void k_out(const float* __restrict__ Wout,
                                             float* __restrict__ out) {
    int mt = blockIdx.x, nt = blockIdx.y, kc = blockIdx.z;
    __shared__ __align__(16) float Ys[32][68];
    __shared__ __align__(16) float Ws[32][68];
    int tid = threadIdx.x;
    int tx = tid & 7, ty = tid >> 3;
    int m0 = ty * 4, n0 = tx * 8;
    ull acc[4][4];
#pragma unroll
    for (int i = 0; i < 4; i++)
#pragma unroll
        for (int j = 0; j < 4; j++) acc[i][j] = 0ull;

#pragma unroll 1
    for (int ck = 0; ck < 4; ck++) {
        int kbase = kc * 128 + ck * 32;
#pragma unroll
        for (int jj = 0; jj < 4; jj++) {
            int idx = tid + jj * 128;
            int m = idx >> 3, kq = idx & 7;
            float4 v = *(const float4*)(d_yg + (size_t)(mt * 64 + m) * 1024 + kbase + kq * 4);
            Ys[kq * 4 + 0][m] = v.x; Ys[kq * 4 + 1][m] = v.y;
            Ys[kq * 4 + 2][m] = v.z; Ys[kq * 4 + 3][m] = v.w;
            float4 w = *(const float4*)(Wout + (size_t)(nt * 64 + m) * 1024 + kbase + kq * 4);
            Ws[kq * 4 + 0][m] = w.x; Ws[kq * 4 + 1][m] = w.y;
            Ws[kq * 4 + 2][m] = w.z; Ws[kq * 4 + 3][m] = w.w;
        }
        __syncthreads();
#pragma unroll
        for (int k = 0; k < 32; k++) {
            float4 yv = *(const float4*)&Ys[k][m0];
            ull yb0 = f2pk(yv.x, yv.x), yb1 = f2pk(yv.y, yv.y);
            ull yb2 = f2pk(yv.z, yv.z), yb3 = f2pk(yv.w, yv.w);
            const ull* wp = (const ull*)&Ws[k][n0];
            ull w0 = wp[0], w1 = wp[1], w2 = wp[2], w3 = wp[3];
            acc[0][0] = ffma2(yb0, w0, acc[0][0]); acc[0][1] = ffma2(yb0, w1, acc[0][1]);
            acc[0][2] = ffma2(yb0, w2, acc[0][2]); acc[0][3] = ffma2(yb0, w3, acc[0][3]);
            acc[1][0] = ffma2(yb1, w0, acc[1][0]); acc[1][1] = ffma2(yb1, w1, acc[1][1]);
            acc[1][2] = ffma2(yb1, w2, acc[1][2]); acc[1][3] = ffma2(yb1, w3, acc[1][3]);
            acc[2][0] = ffma2(yb2, w0, acc[2][0]); acc[2][1] = ffma2(yb2, w1, acc[2][1]);
            acc[2][2] = ffma2(yb2, w2, acc[2][2]); acc[2][3] = ffma2(yb2, w3, acc[2][3]);
            acc[3][0] = ffma2(yb3, w0, acc[3][0]); acc[3][1] = ffma2(yb3, w1, acc[3][1]);
            acc[3][2] = ffma2(yb3, w2, acc[3][2]); acc[3][3] = ffma2(yb3, w3, acc[3][3]);
        }
        __syncthreads();
    }
#pragma unroll
    for (int i = 0; i < 4; i++) {
        float* dst = out + (size_t)(mt * 64 + m0 + i) * 128 + nt * 64 + n0;
#pragma unroll
        for (int j = 0; j < 4; j++) {
            float2 f = f2up(acc[i][j]);
            atomicAdd(dst + 2 * j,     f.x);
            atomicAdd(dst + 2 * j + 1, f.y);
        }
    }
}

// ---------------- launch: 4 kernels, no memset ----------------
extern "C" void kernel_launch(void* const* d_in, const int* in_sizes, int n_in,
                              void* d_out, int out_size) {
    const float* x     = (const float*)d_in[0];
    const float* cosb  = (const float*)d_in[1];
    const float* sinb  = (const float*)d_in[2];
    const float* sink  = (const float*)d_in[3];
    const float* Wqkvg = (const float*)d_in[4];
    const float* pw    = (const float*)d_in[5];
    const float* Wout  = (const float*)d_in[6];
    const float* tao   = (const float*)d_in[7];
    float* out = (float*)d_out;

    k_score<<<512, 256>>>(x, pw, out);
    k_qkvg<<<dim3(32, 8), 256>>>(x, Wqkvg, cosb, sinb, tao, sink);
    k_attn<<<dim3(2, 64), 256>>>();
    k_out<<<dim3(8, 2, 8), 128>>>(Wout, out);
}